// round 8
// baseline (speedup 1.0000x reference)
#include <cuda_runtime.h>
#include <math.h>

// Problem constants
#define HH 128
#define WW 128
#define CH 128
#define NP 16384          // H*W pixels
#define KK 9
#define KDIM 1152         // 9*128
#define EPS 1e-5f
#define IMG 5
#define IMGSTR (NP * CH)  // per-image plane stride (2M floats)

struct Ptr5 { const float* p[5]; };

__device__ const int d_Co[5]   = {20, 80, 150, 210, 308};
__device__ const int d_coff[5] = {0, 20, 100, 250, 460};
__device__ const int d_Npad[5] = {128, 128, 256, 256, 384};

// ---------------- scratch (static device globals; no allocation) -------------
__device__ float g_om[IMG * IMGSTR];      // conv3x3 outputs
__device__ float g_raw[IMG * IMGSTR];     // pre-norm deform outputs
__device__ float g_y1[IMG * IMGSTR];      // block1 outputs
__device__ float g_y2[IMG * IMGSTR];      // block2 outputs
__device__ float g_offm[IMG * IMGSTR];    // offset/mask logits (padded 128)
__device__ float g_wt1[KK * CH * CH];     // transposed conv weights, block1
__device__ float g_wt2[KK * CH * CH];     // transposed conv weights, block2
__device__ float g_owmw[CH * 128];        // padded offset/mask weight [c][j]
__device__ float g_part[IMG * 128 * CH * 2];
__device__ float g_ab[IMG * CH * 2];
__device__ float g_acat[IMG * NP * 256];  // [xc | xin]
__device__ float g_bproj[IMG * 256 * 384];
__device__ float g_ptmp[IMG * NP * 384];  // projection GEMM outputs

// ---------------- weight transpose: cw (O,C,3,3) -> wt[k][c][o] --------------
__global__ void wt_kernel(const float* __restrict__ cw, float* __restrict__ wt) {
    int i = blockIdx.x * 256 + threadIdx.x;   // KK*CH*CH = 147456
    if (i >= KK * CH * CH) return;
    int o = i & 127;
    int kc = i >> 7;
    int c = kc & 127;
    int k = kc >> 7;
    wt[i] = cw[((o << 7) + c) * 9 + k];
}

// ------ pad offset/mask weights: B[c][j] = ow[j][c] (j<18) / mw[j-18][c] -----
__global__ void padow_kernel(const float* __restrict__ ow, const float* __restrict__ mw,
                             float* __restrict__ Bp) {
    int i = blockIdx.x * 256 + threadIdx.x;   // 16384
    int j = i & 127;
    int c = i >> 7;
    float v = 0.f;
    if (j < 18) v = ow[j * 128 + c];
    else if (j < 27) v = mw[(j - 18) * 128 + c];
    Bp[i] = v;
}

// ---- shared 16-step FMA block on one (As,Bs) stage --------------------------
__device__ __forceinline__ void mm16(const float (*__restrict__ As)[128],
                                     const float (*__restrict__ Bs)[128],
                                     float acc[8][8], int ty, int tx) {
#pragma unroll
    for (int kk = 0; kk < 16; kk++) {
        float4 av0 = *(const float4*)&As[kk][ty * 8];
        float4 av1 = *(const float4*)&As[kk][ty * 8 + 4];
        float4 bv0 = *(const float4*)&Bs[kk][tx * 8];
        float4 bv1 = *(const float4*)&Bs[kk][tx * 8 + 4];
        float a[8] = {av0.x, av0.y, av0.z, av0.w, av1.x, av1.y, av1.z, av1.w};
        float b[8] = {bv0.x, bv0.y, bv0.z, bv0.w, bv1.x, bv1.y, bv1.z, bv1.w};
#pragma unroll
        for (int i = 0; i < 8; i++)
#pragma unroll
            for (int j = 0; j < 8; j++) acc[i][j] += a[i] * b[j];
    }
}

// =========== batched tiled fp32 GEMM =========================================
// C[img][M,Ntot] = A[img][M,Kd] @ B[img][Kd,Ntot]; grid (Mtiles, Ntiles, IMG).
// Per-image Ntot tile guard via nguard (0 = none).
// __launch_bounds__(256,2): cap regs at 128 so 2 CTAs co-reside per SM.
__global__ void __launch_bounds__(256, 2) gemm_kernel(const float* __restrict__ A,
                                                      const float* __restrict__ B,
                                                      const float* __restrict__ bias,
                                                      float* __restrict__ C,
                                                      int Kd, int Ntot,
                                                      size_t Astr, size_t Bstr, size_t Cstr,
                                                      int use_nguard) {
    const int img = blockIdx.z;
    if (use_nguard && (int)(blockIdx.y * 128) >= d_Npad[img]) return;
    A += (size_t)img * Astr;
    B += (size_t)img * Bstr;
    C += (size_t)img * Cstr;
    __shared__ float As[2][16][128];
    __shared__ float Bs[2][16][128];
    const int tid = threadIdx.x;
    const int row0 = blockIdx.x * 128;
    const int col0 = blockIdx.y * 128;
    const int tx = tid & 15;
    const int ty = tid >> 4;
    const int am = tid >> 1;
    const int ak = (tid & 1) << 3;
    const int bk = tid >> 4;
    const int bn = (tid & 15) << 3;

    float acc[8][8];
#pragma unroll
    for (int i = 0; i < 8; i++)
#pragma unroll
        for (int j = 0; j < 8; j++) acc[i][j] = 0.f;

    const float* Aptr = A + (size_t)(row0 + am) * Kd + ak;
    const float* Bptr = B + (size_t)bk * Ntot + col0 + bn;

    float4 a0 = *(const float4*)(Aptr);
    float4 a1 = *(const float4*)(Aptr + 4);
    float4 b0 = *(const float4*)(Bptr);
    float4 b1 = *(const float4*)(Bptr + 4);
    As[0][ak + 0][am] = a0.x; As[0][ak + 1][am] = a0.y;
    As[0][ak + 2][am] = a0.z; As[0][ak + 3][am] = a0.w;
    As[0][ak + 4][am] = a1.x; As[0][ak + 5][am] = a1.y;
    As[0][ak + 6][am] = a1.z; As[0][ak + 7][am] = a1.w;
    *(float4*)&Bs[0][bk][bn] = b0;
    *(float4*)&Bs[0][bk][bn + 4] = b1;
    __syncthreads();

    int buf = 0;
    for (int k0 = 16; k0 < Kd; k0 += 16) {
        a0 = *(const float4*)(Aptr + k0);
        a1 = *(const float4*)(Aptr + k0 + 4);
        const float* bp = Bptr + (size_t)k0 * Ntot;
        b0 = *(const float4*)bp;
        b1 = *(const float4*)(bp + 4);
        mm16(As[buf], Bs[buf], acc, ty, tx);
        int nb = buf ^ 1;
        As[nb][ak + 0][am] = a0.x; As[nb][ak + 1][am] = a0.y;
        As[nb][ak + 2][am] = a0.z; As[nb][ak + 3][am] = a0.w;
        As[nb][ak + 4][am] = a1.x; As[nb][ak + 5][am] = a1.y;
        As[nb][ak + 6][am] = a1.z; As[nb][ak + 7][am] = a1.w;
        *(float4*)&Bs[nb][bk][bn] = b0;
        *(float4*)&Bs[nb][bk][bn + 4] = b1;
        __syncthreads();
        buf = nb;
    }
    mm16(As[buf], Bs[buf], acc, ty, tx);

    float bb[8] = {0.f, 0.f, 0.f, 0.f, 0.f, 0.f, 0.f, 0.f};
    if (bias) {
        float4 c0 = *(const float4*)&bias[col0 + tx * 8];
        float4 c1 = *(const float4*)&bias[col0 + tx * 8 + 4];
        bb[0] = c0.x; bb[1] = c0.y; bb[2] = c0.z; bb[3] = c0.w;
        bb[4] = c1.x; bb[5] = c1.y; bb[6] = c1.z; bb[7] = c1.w;
    }
#pragma unroll
    for (int i = 0; i < 8; i++) {
        int row = row0 + ty * 8 + i;
        float4 v0 = make_float4(acc[i][0] + bb[0], acc[i][1] + bb[1],
                                acc[i][2] + bb[2], acc[i][3] + bb[3]);
        float4 v1 = make_float4(acc[i][4] + bb[4], acc[i][5] + bb[5],
                                acc[i][6] + bb[6], acc[i][7] + bb[7]);
        *(float4*)&C[(size_t)row * Ntot + col0 + tx * 8] = v0;
        *(float4*)&C[(size_t)row * Ntot + col0 + tx * 8 + 4] = v1;
    }
}

// ====== batched fused im2col conv3x3 GEMM: grid (128 rows, IMG) ==============
__global__ void __launch_bounds__(256, 2) gemm_conv_kernel(Ptr5 xs,
                                                           const float* __restrict__ B,
                                                           const float* __restrict__ bias,
                                                           float* __restrict__ C) {
    const int img = blockIdx.y;
    const float* __restrict__ x = xs.p[img];
    C += (size_t)img * IMGSTR;
    __shared__ float As[2][16][128];
    __shared__ float Bs[2][16][128];
    const int tid = threadIdx.x;
    const int h = blockIdx.x;
    const int tx = tid & 15;
    const int ty = tid >> 4;
    const int am = tid >> 1;
    const int ak = (tid & 1) << 3;
    const int bk = tid >> 4;
    const int bn = (tid & 15) << 3;

    float acc[8][8];
#pragma unroll
    for (int i = 0; i < 8; i++)
#pragma unroll
        for (int j = 0; j < 8; j++) acc[i][j] = 0.f;

    const float* Bptr = B + (size_t)bk * 128 + bn;

    auto loadA = [&](int k0, float4& o0, float4& o1) {
        int tap = k0 >> 7;
        int c0 = (k0 & 127) + ak;
        int hh = h + tap / 3 - 1;
        int wcol = am + tap % 3 - 1;
        o0 = make_float4(0.f, 0.f, 0.f, 0.f);
        o1 = make_float4(0.f, 0.f, 0.f, 0.f);
        if ((unsigned)hh < 128u && (unsigned)wcol < 128u) {
            const float* xp = x + ((((hh << 7) + wcol)) << 7) + c0;
            o0 = *(const float4*)xp;
            o1 = *(const float4*)(xp + 4);
        }
    };

    float4 a0, a1;
    loadA(0, a0, a1);
    float4 b0 = *(const float4*)(Bptr);
    float4 b1 = *(const float4*)(Bptr + 4);
    As[0][ak + 0][am] = a0.x; As[0][ak + 1][am] = a0.y;
    As[0][ak + 2][am] = a0.z; As[0][ak + 3][am] = a0.w;
    As[0][ak + 4][am] = a1.x; As[0][ak + 5][am] = a1.y;
    As[0][ak + 6][am] = a1.z; As[0][ak + 7][am] = a1.w;
    *(float4*)&Bs[0][bk][bn] = b0;
    *(float4*)&Bs[0][bk][bn + 4] = b1;
    __syncthreads();

    int buf = 0;
    for (int k0 = 16; k0 < KDIM; k0 += 16) {
        loadA(k0, a0, a1);
        const float* bp = Bptr + (size_t)k0 * 128;
        b0 = *(const float4*)bp;
        b1 = *(const float4*)(bp + 4);
        mm16(As[buf], Bs[buf], acc, ty, tx);
        int nb = buf ^ 1;
        As[nb][ak + 0][am] = a0.x; As[nb][ak + 1][am] = a0.y;
        As[nb][ak + 2][am] = a0.z; As[nb][ak + 3][am] = a0.w;
        As[nb][ak + 4][am] = a1.x; As[nb][ak + 5][am] = a1.y;
        As[nb][ak + 6][am] = a1.z; As[nb][ak + 7][am] = a1.w;
        *(float4*)&Bs[nb][bk][bn] = b0;
        *(float4*)&Bs[nb][bk][bn + 4] = b1;
        __syncthreads();
        buf = nb;
    }
    mm16(As[buf], Bs[buf], acc, ty, tx);

    float4 c0 = *(const float4*)&bias[tx * 8];
    float4 c1 = *(const float4*)&bias[tx * 8 + 4];
    float bb[8] = {c0.x, c0.y, c0.z, c0.w, c1.x, c1.y, c1.z, c1.w};
#pragma unroll
    for (int i = 0; i < 8; i++) {
        int p = (h << 7) + ty * 8 + i;
        float4 v0 = make_float4(acc[i][0] + bb[0], acc[i][1] + bb[1],
                                acc[i][2] + bb[2], acc[i][3] + bb[3]);
        float4 v1 = make_float4(acc[i][4] + bb[4], acc[i][5] + bb[5],
                                acc[i][6] + bb[6], acc[i][7] + bb[7]);
        *(float4*)&C[(size_t)p * 128 + tx * 8] = v0;
        *(float4*)&C[(size_t)p * 128 + tx * 8 + 4] = v1;
    }
}

// ====== batched fused deformable-sample GEMM: grid (128 rows, IMG) ===========
// Software-pipelined: gathers for chunk k+1 issue before mm16 of chunk k.
// (keeps its own register budget; 1 CTA/SM)
__global__ void __launch_bounds__(256) gemm_deform_kernel(Ptr5 xs,
                                                          const float* __restrict__ offm,
                                                          const float* __restrict__ B,
                                                          const float* __restrict__ bias,
                                                          float* __restrict__ C) {
    const int img = blockIdx.y;
    const float* __restrict__ x = xs.p[img];
    offm += (size_t)img * IMGSTR;
    C += (size_t)img * IMGSTR;
    __shared__ float As[16][128];
    __shared__ float Bs[16][128];
    __shared__ float4 w4_s[9][128];
    __shared__ int iy_s[9][128];
    __shared__ int ix_s[9][128];
    const int tid = threadIdx.x;
    const int h = blockIdx.x;
    const int tx = tid & 15;
    const int ty = tid >> 4;
    const int am = tid >> 1;
    const int ak = (tid & 1) << 3;
    const int bk = tid >> 4;
    const int bn = (tid & 15) << 3;

    if (tid < 128) {
        int w = tid;
        const float* d = &offm[((size_t)((h << 7) + w)) * 128];
        float mx = d[18];
#pragma unroll
        for (int k = 1; k < 9; k++) mx = fmaxf(mx, d[18 + k]);
        float e[9];
        float ssum = 0.f;
#pragma unroll
        for (int k = 0; k < 9; k++) { e[k] = expf(d[18 + k] - mx); ssum += e[k]; }
        float r = 1.f / ssum;
#pragma unroll
        for (int k = 0; k < 9; k++) {
            float m = e[k] * r;
            float py = (float)(h - 1 + k / 3) + d[2 * k];
            float px = (float)(w - 1 + k % 3) + d[2 * k + 1];
            float y0f = floorf(py), x0f = floorf(px);
            float wy1 = py - y0f, wy0 = 1.f - wy1;
            float wx1 = px - x0f, wx0 = 1.f - wx1;
            int y0 = (int)y0f, x0 = (int)x0f;
            float vy0 = ((unsigned)y0 < 128u) ? 1.f : 0.f;
            float vy1 = ((unsigned)(y0 + 1) < 128u) ? 1.f : 0.f;
            float vx0 = ((unsigned)x0 < 128u) ? 1.f : 0.f;
            float vx1 = ((unsigned)(x0 + 1) < 128u) ? 1.f : 0.f;
            w4_s[k][w] = make_float4(wy0 * wx0 * vy0 * vx0 * m,
                                     wy0 * wx1 * vy0 * vx1 * m,
                                     wy1 * wx0 * vy1 * vx0 * m,
                                     wy1 * wx1 * vy1 * vx1 * m);
            iy_s[k][w] = y0;
            ix_s[k][w] = x0;
        }
    }
    __syncthreads();

    float acc[8][8];
#pragma unroll
    for (int i = 0; i < 8; i++)
#pragma unroll
        for (int j = 0; j < 8; j++) acc[i][j] = 0.f;

    const float* Bptr = B + (size_t)bk * 128 + bn;

    float4 v00, v01, v10, v11, u00, u01, u10, u11, b0r, b1r;
    auto gload = [&](int k0) {
        int tap = k0 >> 7;
        int c0 = (k0 & 127) + ak;
        int y0 = iy_s[tap][am];
        int x0 = ix_s[tap][am];
        int y0c = min(max(y0, 0), 127);
        int y1c = min(max(y0 + 1, 0), 127);
        int x0c = min(max(x0, 0), 127);
        int x1c = min(max(x0 + 1, 0), 127);
        const float* p00 = x + ((((y0c << 7) + x0c) << 7) + c0);
        const float* p01 = x + ((((y0c << 7) + x1c) << 7) + c0);
        const float* p10 = x + ((((y1c << 7) + x0c) << 7) + c0);
        const float* p11 = x + ((((y1c << 7) + x1c) << 7) + c0);
        v00 = *(const float4*)p00;
        v01 = *(const float4*)p01;
        v10 = *(const float4*)p10;
        v11 = *(const float4*)p11;
        u00 = *(const float4*)(p00 + 4);
        u01 = *(const float4*)(p01 + 4);
        u10 = *(const float4*)(p10 + 4);
        u11 = *(const float4*)(p11 + 4);
        const float* bp = Bptr + (size_t)k0 * 128;
        b0r = *(const float4*)bp;
        b1r = *(const float4*)(bp + 4);
    };

    gload(0);
    for (int k0 = 0; k0 < KDIM; k0 += 16) {
        float4 wg = w4_s[k0 >> 7][am];
        As[ak + 0][am] = wg.x * v00.x + wg.y * v01.x + wg.z * v10.x + wg.w * v11.x;
        As[ak + 1][am] = wg.x * v00.y + wg.y * v01.y + wg.z * v10.y + wg.w * v11.y;
        As[ak + 2][am] = wg.x * v00.z + wg.y * v01.z + wg.z * v10.z + wg.w * v11.z;
        As[ak + 3][am] = wg.x * v00.w + wg.y * v01.w + wg.z * v10.w + wg.w * v11.w;
        As[ak + 4][am] = wg.x * u00.x + wg.y * u01.x + wg.z * u10.x + wg.w * u11.x;
        As[ak + 5][am] = wg.x * u00.y + wg.y * u01.y + wg.z * u10.y + wg.w * u11.y;
        As[ak + 6][am] = wg.x * u00.z + wg.y * u01.z + wg.z * u10.z + wg.w * u11.z;
        As[ak + 7][am] = wg.x * u00.w + wg.y * u01.w + wg.z * u10.w + wg.w * u11.w;
        *(float4*)&Bs[bk][bn] = b0r;
        *(float4*)&Bs[bk][bn + 4] = b1r;
        __syncthreads();
        if (k0 + 16 < KDIM) gload(k0 + 16);
        mm16(As, Bs, acc, ty, tx);
        if (k0 + 16 < KDIM) __syncthreads();
    }

    float4 c0v = *(const float4*)&bias[tx * 8];
    float4 c1v = *(const float4*)&bias[tx * 8 + 4];
    float bb[8] = {c0v.x, c0v.y, c0v.z, c0v.w, c1v.x, c1v.y, c1v.z, c1v.w};
#pragma unroll
    for (int i = 0; i < 8; i++) {
        int p = (h << 7) + ty * 8 + i;
        float4 v0 = make_float4(acc[i][0] + bb[0], acc[i][1] + bb[1],
                                acc[i][2] + bb[2], acc[i][3] + bb[3]);
        float4 v1 = make_float4(acc[i][4] + bb[4], acc[i][5] + bb[5],
                                acc[i][6] + bb[6], acc[i][7] + bb[7]);
        *(float4*)&C[(size_t)p * 128 + tx * 8] = v0;
        *(float4*)&C[(size_t)p * 128 + tx * 8 + 4] = v1;
    }
}

// ------------- instance-norm: deterministic two-stage reduction (batched) ----
__global__ void __launch_bounds__(128) stats_part_kernel(const float* __restrict__ raw,
                                                         float* __restrict__ part) {
    const int img = blockIdx.y;
    raw += (size_t)img * IMGSTR;
    part += (size_t)img * 128 * CH * 2;
    int c = threadIdx.x;
    int b = blockIdx.x;
    float s = 0.f, q = 0.f;
    for (int p = b * 128; p < (b + 1) * 128; p++) {
        float v = raw[(size_t)p * 128 + c];
        s += v;
        q += v * v;
    }
    part[(size_t)(b * 128 + c) * 2 + 0] = s;
    part[(size_t)(b * 128 + c) * 2 + 1] = q;
}

__global__ void __launch_bounds__(128) stats_final_kernel(const float* __restrict__ part,
                                                          const float* __restrict__ bg,
                                                          const float* __restrict__ bb,
                                                          float* __restrict__ ab) {
    const int img = blockIdx.x;
    part += (size_t)img * 128 * CH * 2;
    ab += (size_t)img * CH * 2;
    int c = threadIdx.x;
    float s = 0.f, q = 0.f;
    for (int b = 0; b < 128; b++) {
        s += part[(size_t)(b * 128 + c) * 2 + 0];
        q += part[(size_t)(b * 128 + c) * 2 + 1];
    }
    float mu = s * (1.f / 16384.f);
    float var = q * (1.f / 16384.f) - mu * mu;
    float inv = rsqrtf(var + EPS);
    float a = inv * bg[c];
    ab[c * 2 + 0] = a;
    ab[c * 2 + 1] = bb[c] - mu * a;
}

__global__ void __launch_bounds__(256) norm_relu_kernel(const float* __restrict__ raw,
                                                        const float* __restrict__ ab,
                                                        float* __restrict__ y) {
    const int img = blockIdx.y;
    raw += (size_t)img * IMGSTR;
    y += (size_t)img * IMGSTR;
    ab += (size_t)img * CH * 2;
    int i = blockIdx.x * 256 + threadIdx.x;
    int c = i & 127;
    float v = raw[i] * ab[c * 2] + ab[c * 2 + 1];
    y[i] = v > 0.f ? v : 0.f;
}

// ------------- projection helpers (batched) ----------------------------------
__global__ void __launch_bounds__(128) acat_kernel(const float* __restrict__ xc,
                                                   Ptr5 xs, float* __restrict__ A) {
    const int img = blockIdx.y;
    xc += (size_t)img * IMGSTR;
    A += (size_t)img * NP * 256;
    const float* xin = xs.p[img];
    int p = blockIdx.x;
    int t = threadIdx.x;
    A[(size_t)p * 256 + t] = xc[(size_t)p * 128 + t];
    A[(size_t)p * 256 + 128 + t] = xin[(size_t)p * 128 + t];
}

// all-image padded projection weight: Bp[img][c][o], 256x384, zero padded
__global__ void bproj_kernel(Ptr5 wA, Ptr5 wB, float* __restrict__ Bp) {
    int i = blockIdx.x * 256 + threadIdx.x;   // 5*256*384 = 491520
    if (i >= IMG * 256 * 384) return;
    int img = i / (256 * 384);
    int r = i % (256 * 384);
    int o = r % 384;
    int c = r / 384;
    float v = 0.f;
    if (o < d_Co[img]) {
        if (c < 128) v = wA.p[img][o * 128 + c];
        else if (wB.p[img]) v = wB.p[img][o * 128 + (c - 128)];
    }
    Bp[i] = v;
}

// tmp[img][p][o] (384 stride) -> out NCHW at channel offset coff[img]
__global__ void proj_copy_kernel(const float* __restrict__ tmp, float* __restrict__ out) {
    const int img = blockIdx.y;
    int idx = blockIdx.x * 256 + threadIdx.x;   // up to 308*16384
    int Co = d_Co[img];
    if (idx >= Co * NP) return;
    int o = idx >> 14;
    int p = idx & 16383;
    out[(size_t)(d_coff[img] + o) * NP + p] =
        tmp[(size_t)img * NP * 384 + (size_t)p * 384 + o];
}

// ------------- final layernorm over W (rows of 128) --------------------------
__global__ void __launch_bounds__(256) final_ln_kernel(float* __restrict__ out,
                                                       const float* __restrict__ lnw,
                                                       const float* __restrict__ lnb) {
    int row = blockIdx.x * 8 + (threadIdx.x >> 5);  // 768*128 rows
    int lane = threadIdx.x & 31;
    float* rp = &out[(size_t)row * 128];
    float4 v = *(const float4*)&rp[lane * 4];
    float s = v.x + v.y + v.z + v.w;
    float q = v.x * v.x + v.y * v.y + v.z * v.z + v.w * v.w;
#pragma unroll
    for (int o = 16; o; o >>= 1) {
        s += __shfl_xor_sync(0xffffffffu, s, o);
        q += __shfl_xor_sync(0xffffffffu, q, o);
    }
    float mu = s * (1.f / 128.f);
    float var = q * (1.f / 128.f) - mu * mu;
    float inv = rsqrtf(var + EPS);
    float4 g = *(const float4*)&lnw[lane * 4];
    float4 b = *(const float4*)&lnb[lane * 4];
    v.x = (v.x - mu) * inv * g.x + b.x;
    v.y = (v.y - mu) * inv * g.y + b.y;
    v.z = (v.z - mu) * inv * g.z + b.z;
    v.w = (v.w - mu) * inv * g.w + b.w;
    *(float4*)&rp[lane * 4] = v;
}

// =============================================================================
#define SYM(p, s) do { void* _t = 0; cudaGetSymbolAddress(&_t, s); (p) = (float*)_t; } while (0)

static void run_block(Ptr5 xin, const float* wt, const float* cb,
                      const float* bg, const float* bb, float* yout,
                      float* pom, float* praw, float* ppart,
                      float* pab, float* powmw, float* poffm) {
    gemm_conv_kernel<<<dim3(128, IMG), 256>>>(xin, wt, cb, pom);
    gemm_kernel<<<dim3(128, 1, IMG), 256>>>(pom, powmw, 0, poffm, 128, 128,
                                            IMGSTR, 0, IMGSTR, 0);
    gemm_deform_kernel<<<dim3(128, IMG), 256>>>(xin, poffm, wt, cb, praw);
    stats_part_kernel<<<dim3(128, IMG), 128>>>(praw, ppart);
    stats_final_kernel<<<IMG, 128>>>(ppart, bg, bb, pab);
    norm_relu_kernel<<<dim3(IMGSTR / 256, IMG), 256>>>(praw, pab, yout);
}

extern "C" void kernel_launch(void* const* d_in, const int* in_sizes, int n_in,
                              void* d_out, int out_size) {
    (void)in_sizes; (void)n_in; (void)out_size;
    Ptr5 xs;
    for (int i = 0; i < 5; i++) xs.p[i] = (const float*)d_in[i];
    const float* b_cw[2] = {(const float*)d_in[5], (const float*)d_in[11]};
    const float* b_cb[2] = {(const float*)d_in[6], (const float*)d_in[12]};
    const float* b_ow[2] = {(const float*)d_in[7], (const float*)d_in[13]};
    const float* b_mw[2] = {(const float*)d_in[8], (const float*)d_in[14]};
    const float* b_bg[2] = {(const float*)d_in[9], (const float*)d_in[15]};
    const float* b_bb[2] = {(const float*)d_in[10], (const float*)d_in[16]};
    Ptr5 wA, wB;
    wA.p[0] = (const float*)d_in[17]; wB.p[0] = 0;
    wA.p[1] = (const float*)d_in[18]; wB.p[1] = 0;
    wA.p[2] = (const float*)d_in[19]; wB.p[2] = (const float*)d_in[20];
    wA.p[3] = (const float*)d_in[21]; wB.p[3] = (const float*)d_in[22];
    wA.p[4] = (const float*)d_in[23]; wB.p[4] = (const float*)d_in[24];
    const float* lnw = (const float*)d_in[25];
    const float* lnb = (const float*)d_in[26];
    float* out = (float*)d_out;

    float *pom, *praw, *py1, *py2, *pwt1, *pwt2, *ppart, *pab, *pacat,
          *pbproj, *pptmp, *powmw, *poffm;
    SYM(pom, g_om);   SYM(praw, g_raw);
    SYM(py1, g_y1);   SYM(py2, g_y2);   SYM(pwt1, g_wt1);  SYM(pwt2, g_wt2);
    SYM(ppart, g_part); SYM(pab, g_ab); SYM(pacat, g_acat);
    SYM(pbproj, g_bproj); SYM(pptmp, g_ptmp); SYM(powmw, g_owmw);
    SYM(poffm, g_offm);

    wt_kernel<<<576, 256>>>(b_cw[0], pwt1);
    wt_kernel<<<576, 256>>>(b_cw[1], pwt2);

    Ptr5 y1p;
    for (int i = 0; i < 5; i++) y1p.p[i] = py1 + (size_t)i * IMGSTR;

    // block 1 (all images)
    padow_kernel<<<64, 256>>>(b_ow[0], b_mw[0], powmw);
    run_block(xs, pwt1, b_cb[0], b_bg[0], b_bb[0], py1,
              pom, praw, ppart, pab, powmw, poffm);
    // block 2 (all images)
    padow_kernel<<<64, 256>>>(b_ow[1], b_mw[1], powmw);
    run_block(y1p, pwt2, b_cb[1], b_bg[1], b_bb[1], py2,
              pom, praw, ppart, pab, powmw, poffm);

    // projections (batched, padded to 256x384 with per-image tile guard)
    acat_kernel<<<dim3(NP, IMG), 128>>>(py2, xs, pacat);
    bproj_kernel<<<(IMG * 256 * 384 + 255) / 256, 256>>>(wA, wB, pbproj);
    gemm_kernel<<<dim3(128, 3, IMG), 256>>>(pacat, pbproj, 0, pptmp, 256, 384,
                                            (size_t)NP * 256, 256 * 384,
                                            (size_t)NP * 384, 1);
    proj_copy_kernel<<<dim3((308 * NP + 255) / 256, IMG), 256>>>(pptmp, out);
    final_ln_kernel<<<768 * 128 / 8, 256>>>(out, lnw, lnb);
}

// round 9
// speedup vs baseline: 1.5068x; 1.5068x over previous
#include <cuda_runtime.h>
#include <math.h>

// Problem constants
#define HH 128
#define WW 128
#define CH 128
#define NP 16384          // H*W pixels
#define KK 9
#define KDIM 1152         // 9*128
#define EPS 1e-5f
#define IMG 5
#define IMGSTR (NP * CH)  // per-image plane stride (2M floats)

struct Ptr5 { const float* p[5]; };

__device__ const int d_Co[5]   = {20, 80, 150, 210, 308};
__device__ const int d_coff[5] = {0, 20, 100, 250, 460};
__device__ const int d_Npad[5] = {128, 128, 256, 256, 384};

// ---------------- scratch (static device globals; no allocation) -------------
__device__ float g_om[IMG * IMGSTR];      // conv3x3 outputs
__device__ float g_raw[IMG * IMGSTR];     // pre-norm deform outputs
__device__ float g_y1[IMG * IMGSTR];      // block1 outputs
__device__ float g_y2[IMG * IMGSTR];      // block2 outputs
__device__ float g_offm[IMG * IMGSTR];    // offset/mask logits (padded 128)
__device__ float g_wt1[KK * CH * CH];     // transposed conv weights, block1
__device__ float g_wt2[KK * CH * CH];     // transposed conv weights, block2
__device__ float g_owmw[CH * 128];        // padded offset/mask weight [c][j]
__device__ float g_part[IMG * 128 * CH * 2];
__device__ float g_ab[IMG * CH * 2];
__device__ float g_acat[IMG * NP * 256];  // [xc | xin]
__device__ float g_bproj[IMG * 256 * 384];
__device__ float g_ptmp[IMG * NP * 384];  // projection GEMM outputs

// ---------------- weight transpose: cw (O,C,3,3) -> wt[k][c][o] --------------
__global__ void wt_kernel(const float* __restrict__ cw, float* __restrict__ wt) {
    int i = blockIdx.x * 256 + threadIdx.x;   // KK*CH*CH = 147456
    if (i >= KK * CH * CH) return;
    int o = i & 127;
    int kc = i >> 7;
    int c = kc & 127;
    int k = kc >> 7;
    wt[i] = cw[((o << 7) + c) * 9 + k];
}

// ------ pad offset/mask weights: B[c][j] = ow[j][c] (j<18) / mw[j-18][c] -----
__global__ void padow_kernel(const float* __restrict__ ow, const float* __restrict__ mw,
                             float* __restrict__ Bp) {
    int i = blockIdx.x * 256 + threadIdx.x;   // 16384
    int j = i & 127;
    int c = i >> 7;
    float v = 0.f;
    if (j < 18) v = ow[j * 128 + c];
    else if (j < 27) v = mw[(j - 18) * 128 + c];
    Bp[i] = v;
}

// ---- shared 16-step FMA block on one (As,Bs) stage (A-width templated) ------
template <int AW>
__device__ __forceinline__ void mm16t(const float (*__restrict__ As)[AW],
                                      const float (*__restrict__ Bs)[128],
                                      float acc[8][8], int ty, int tx) {
#pragma unroll
    for (int kk = 0; kk < 16; kk++) {
        float4 av0 = *(const float4*)&As[kk][ty * 8];
        float4 av1 = *(const float4*)&As[kk][ty * 8 + 4];
        float4 bv0 = *(const float4*)&Bs[kk][tx * 8];
        float4 bv1 = *(const float4*)&Bs[kk][tx * 8 + 4];
        float a[8] = {av0.x, av0.y, av0.z, av0.w, av1.x, av1.y, av1.z, av1.w};
        float b[8] = {bv0.x, bv0.y, bv0.z, bv0.w, bv1.x, bv1.y, bv1.z, bv1.w};
#pragma unroll
        for (int i = 0; i < 8; i++)
#pragma unroll
            for (int j = 0; j < 8; j++) acc[i][j] += a[i] * b[j];
    }
}

// =========== batched tiled fp32 GEMM: 64x128 tile, 128 threads ===============
// C[img][M,Ntot] = A[img][M,Kd] @ B[img][Kd,Ntot]; grid (M/64, Ntot/128, IMG).
// 8x8 per-thread tile, double-buffered; ~3 CTAs co-reside per SM naturally.
__global__ void __launch_bounds__(128) gemm_kernel(const float* __restrict__ A,
                                                   const float* __restrict__ B,
                                                   const float* __restrict__ bias,
                                                   float* __restrict__ C,
                                                   int Kd, int Ntot,
                                                   size_t Astr, size_t Bstr, size_t Cstr,
                                                   int use_nguard) {
    const int img = blockIdx.z;
    if (use_nguard && (int)(blockIdx.y * 128) >= d_Npad[img]) return;
    A += (size_t)img * Astr;
    B += (size_t)img * Bstr;
    C += (size_t)img * Cstr;
    __shared__ float As[2][16][64];
    __shared__ float Bs[2][16][128];
    const int tid = threadIdx.x;
    const int row0 = blockIdx.x * 64;
    const int col0 = blockIdx.y * 128;
    const int tx = tid & 15;          // col group: cols tx*8..+7
    const int ty = tid >> 4;          // row group: rows ty*8..+7 (0..7 -> 64)
    const int am = tid >> 1;          // A load row (0..63)
    const int ak = (tid & 1) << 3;    // A load k offset (0 or 8)
    const int bk = tid >> 3;          // B load k (0..15)
    const int bn = (tid & 7) << 4;    // B load col offset (0..112 step 16)

    float acc[8][8];
#pragma unroll
    for (int i = 0; i < 8; i++)
#pragma unroll
        for (int j = 0; j < 8; j++) acc[i][j] = 0.f;

    const float* Aptr = A + (size_t)(row0 + am) * Kd + ak;
    const float* Bptr = B + (size_t)bk * Ntot + col0 + bn;

    float4 a0 = *(const float4*)(Aptr);
    float4 a1 = *(const float4*)(Aptr + 4);
    float4 b0 = *(const float4*)(Bptr);
    float4 b1 = *(const float4*)(Bptr + 4);
    float4 b2 = *(const float4*)(Bptr + 8);
    float4 b3 = *(const float4*)(Bptr + 12);
    As[0][ak + 0][am] = a0.x; As[0][ak + 1][am] = a0.y;
    As[0][ak + 2][am] = a0.z; As[0][ak + 3][am] = a0.w;
    As[0][ak + 4][am] = a1.x; As[0][ak + 5][am] = a1.y;
    As[0][ak + 6][am] = a1.z; As[0][ak + 7][am] = a1.w;
    *(float4*)&Bs[0][bk][bn] = b0;
    *(float4*)&Bs[0][bk][bn + 4] = b1;
    *(float4*)&Bs[0][bk][bn + 8] = b2;
    *(float4*)&Bs[0][bk][bn + 12] = b3;
    __syncthreads();

    int buf = 0;
    for (int k0 = 16; k0 < Kd; k0 += 16) {
        a0 = *(const float4*)(Aptr + k0);
        a1 = *(const float4*)(Aptr + k0 + 4);
        const float* bp = Bptr + (size_t)k0 * Ntot;
        b0 = *(const float4*)bp;
        b1 = *(const float4*)(bp + 4);
        b2 = *(const float4*)(bp + 8);
        b3 = *(const float4*)(bp + 12);
        mm16t<64>(As[buf], Bs[buf], acc, ty, tx);
        int nb = buf ^ 1;
        As[nb][ak + 0][am] = a0.x; As[nb][ak + 1][am] = a0.y;
        As[nb][ak + 2][am] = a0.z; As[nb][ak + 3][am] = a0.w;
        As[nb][ak + 4][am] = a1.x; As[nb][ak + 5][am] = a1.y;
        As[nb][ak + 6][am] = a1.z; As[nb][ak + 7][am] = a1.w;
        *(float4*)&Bs[nb][bk][bn] = b0;
        *(float4*)&Bs[nb][bk][bn + 4] = b1;
        *(float4*)&Bs[nb][bk][bn + 8] = b2;
        *(float4*)&Bs[nb][bk][bn + 12] = b3;
        __syncthreads();
        buf = nb;
    }
    mm16t<64>(As[buf], Bs[buf], acc, ty, tx);

    float bb[8] = {0.f, 0.f, 0.f, 0.f, 0.f, 0.f, 0.f, 0.f};
    if (bias) {
        float4 c0 = *(const float4*)&bias[col0 + tx * 8];
        float4 c1 = *(const float4*)&bias[col0 + tx * 8 + 4];
        bb[0] = c0.x; bb[1] = c0.y; bb[2] = c0.z; bb[3] = c0.w;
        bb[4] = c1.x; bb[5] = c1.y; bb[6] = c1.z; bb[7] = c1.w;
    }
#pragma unroll
    for (int i = 0; i < 8; i++) {
        int row = row0 + ty * 8 + i;
        float4 v0 = make_float4(acc[i][0] + bb[0], acc[i][1] + bb[1],
                                acc[i][2] + bb[2], acc[i][3] + bb[3]);
        float4 v1 = make_float4(acc[i][4] + bb[4], acc[i][5] + bb[5],
                                acc[i][6] + bb[6], acc[i][7] + bb[7]);
        *(float4*)&C[(size_t)row * Ntot + col0 + tx * 8] = v0;
        *(float4*)&C[(size_t)row * Ntot + col0 + tx * 8 + 4] = v1;
    }
}

// ====== batched fused im2col conv3x3 GEMM: 64-pixel half-rows ================
// grid (256 half-rows, IMG), 128 threads.
__global__ void __launch_bounds__(128) gemm_conv_kernel(Ptr5 xs,
                                                        const float* __restrict__ B,
                                                        const float* __restrict__ bias,
                                                        float* __restrict__ C) {
    const int img = blockIdx.y;
    const float* __restrict__ x = xs.p[img];
    C += (size_t)img * IMGSTR;
    __shared__ float As[2][16][64];
    __shared__ float Bs[2][16][128];
    const int tid = threadIdx.x;
    const int h = blockIdx.x >> 1;
    const int wbase = (blockIdx.x & 1) << 6;   // 0 or 64
    const int tx = tid & 15;
    const int ty = tid >> 4;
    const int am = tid >> 1;          // pixel within half-row (0..63)
    const int ak = (tid & 1) << 3;
    const int bk = tid >> 3;
    const int bn = (tid & 7) << 4;

    float acc[8][8];
#pragma unroll
    for (int i = 0; i < 8; i++)
#pragma unroll
        for (int j = 0; j < 8; j++) acc[i][j] = 0.f;

    const float* Bptr = B + (size_t)bk * 128 + bn;

    auto loadA = [&](int k0, float4& o0, float4& o1) {
        int tap = k0 >> 7;
        int c0 = (k0 & 127) + ak;
        int hh = h + tap / 3 - 1;
        int wcol = wbase + am + tap % 3 - 1;
        o0 = make_float4(0.f, 0.f, 0.f, 0.f);
        o1 = make_float4(0.f, 0.f, 0.f, 0.f);
        if ((unsigned)hh < 128u && (unsigned)wcol < 128u) {
            const float* xp = x + ((((hh << 7) + wcol)) << 7) + c0;
            o0 = *(const float4*)xp;
            o1 = *(const float4*)(xp + 4);
        }
    };

    float4 a0, a1;
    loadA(0, a0, a1);
    float4 b0 = *(const float4*)(Bptr);
    float4 b1 = *(const float4*)(Bptr + 4);
    float4 b2 = *(const float4*)(Bptr + 8);
    float4 b3 = *(const float4*)(Bptr + 12);
    As[0][ak + 0][am] = a0.x; As[0][ak + 1][am] = a0.y;
    As[0][ak + 2][am] = a0.z; As[0][ak + 3][am] = a0.w;
    As[0][ak + 4][am] = a1.x; As[0][ak + 5][am] = a1.y;
    As[0][ak + 6][am] = a1.z; As[0][ak + 7][am] = a1.w;
    *(float4*)&Bs[0][bk][bn] = b0;
    *(float4*)&Bs[0][bk][bn + 4] = b1;
    *(float4*)&Bs[0][bk][bn + 8] = b2;
    *(float4*)&Bs[0][bk][bn + 12] = b3;
    __syncthreads();

    int buf = 0;
    for (int k0 = 16; k0 < KDIM; k0 += 16) {
        loadA(k0, a0, a1);
        const float* bp = Bptr + (size_t)k0 * 128;
        b0 = *(const float4*)bp;
        b1 = *(const float4*)(bp + 4);
        b2 = *(const float4*)(bp + 8);
        b3 = *(const float4*)(bp + 12);
        mm16t<64>(As[buf], Bs[buf], acc, ty, tx);
        int nb = buf ^ 1;
        As[nb][ak + 0][am] = a0.x; As[nb][ak + 1][am] = a0.y;
        As[nb][ak + 2][am] = a0.z; As[nb][ak + 3][am] = a0.w;
        As[nb][ak + 4][am] = a1.x; As[nb][ak + 5][am] = a1.y;
        As[nb][ak + 6][am] = a1.z; As[nb][ak + 7][am] = a1.w;
        *(float4*)&Bs[nb][bk][bn] = b0;
        *(float4*)&Bs[nb][bk][bn + 4] = b1;
        *(float4*)&Bs[nb][bk][bn + 8] = b2;
        *(float4*)&Bs[nb][bk][bn + 12] = b3;
        __syncthreads();
        buf = nb;
    }
    mm16t<64>(As[buf], Bs[buf], acc, ty, tx);

    float4 c0 = *(const float4*)&bias[tx * 8];
    float4 c1 = *(const float4*)&bias[tx * 8 + 4];
    float bb[8] = {c0.x, c0.y, c0.z, c0.w, c1.x, c1.y, c1.z, c1.w};
#pragma unroll
    for (int i = 0; i < 8; i++) {
        int p = (h << 7) + wbase + ty * 8 + i;
        float4 v0 = make_float4(acc[i][0] + bb[0], acc[i][1] + bb[1],
                                acc[i][2] + bb[2], acc[i][3] + bb[3]);
        float4 v1 = make_float4(acc[i][4] + bb[4], acc[i][5] + bb[5],
                                acc[i][6] + bb[6], acc[i][7] + bb[7]);
        *(float4*)&C[(size_t)p * 128 + tx * 8] = v0;
        *(float4*)&C[(size_t)p * 128 + tx * 8 + 4] = v1;
    }
}

// ====== batched fused deformable-sample GEMM: grid (128 rows, IMG) ===========
// Software-pipelined; unchanged from the measured 3504us configuration.
__global__ void __launch_bounds__(256) gemm_deform_kernel(Ptr5 xs,
                                                          const float* __restrict__ offm,
                                                          const float* __restrict__ B,
                                                          const float* __restrict__ bias,
                                                          float* __restrict__ C) {
    const int img = blockIdx.y;
    const float* __restrict__ x = xs.p[img];
    offm += (size_t)img * IMGSTR;
    C += (size_t)img * IMGSTR;
    __shared__ float As[16][128];
    __shared__ float Bs[16][128];
    __shared__ float4 w4_s[9][128];
    __shared__ int iy_s[9][128];
    __shared__ int ix_s[9][128];
    const int tid = threadIdx.x;
    const int h = blockIdx.x;
    const int tx = tid & 15;
    const int ty = tid >> 4;
    const int am = tid >> 1;
    const int ak = (tid & 1) << 3;
    const int bk = tid >> 4;
    const int bn = (tid & 15) << 3;

    if (tid < 128) {
        int w = tid;
        const float* d = &offm[((size_t)((h << 7) + w)) * 128];
        float mx = d[18];
#pragma unroll
        for (int k = 1; k < 9; k++) mx = fmaxf(mx, d[18 + k]);
        float e[9];
        float ssum = 0.f;
#pragma unroll
        for (int k = 0; k < 9; k++) { e[k] = expf(d[18 + k] - mx); ssum += e[k]; }
        float r = 1.f / ssum;
#pragma unroll
        for (int k = 0; k < 9; k++) {
            float m = e[k] * r;
            float py = (float)(h - 1 + k / 3) + d[2 * k];
            float px = (float)(w - 1 + k % 3) + d[2 * k + 1];
            float y0f = floorf(py), x0f = floorf(px);
            float wy1 = py - y0f, wy0 = 1.f - wy1;
            float wx1 = px - x0f, wx0 = 1.f - wx1;
            int y0 = (int)y0f, x0 = (int)x0f;
            float vy0 = ((unsigned)y0 < 128u) ? 1.f : 0.f;
            float vy1 = ((unsigned)(y0 + 1) < 128u) ? 1.f : 0.f;
            float vx0 = ((unsigned)x0 < 128u) ? 1.f : 0.f;
            float vx1 = ((unsigned)(x0 + 1) < 128u) ? 1.f : 0.f;
            w4_s[k][w] = make_float4(wy0 * wx0 * vy0 * vx0 * m,
                                     wy0 * wx1 * vy0 * vx1 * m,
                                     wy1 * wx0 * vy1 * vx0 * m,
                                     wy1 * wx1 * vy1 * vx1 * m);
            iy_s[k][w] = y0;
            ix_s[k][w] = x0;
        }
    }
    __syncthreads();

    float acc[8][8];
#pragma unroll
    for (int i = 0; i < 8; i++)
#pragma unroll
        for (int j = 0; j < 8; j++) acc[i][j] = 0.f;

    const float* Bptr = B + (size_t)bk * 128 + bn;

    float4 v00, v01, v10, v11, u00, u01, u10, u11, b0r, b1r;
    auto gload = [&](int k0) {
        int tap = k0 >> 7;
        int c0 = (k0 & 127) + ak;
        int y0 = iy_s[tap][am];
        int x0 = ix_s[tap][am];
        int y0c = min(max(y0, 0), 127);
        int y1c = min(max(y0 + 1, 0), 127);
        int x0c = min(max(x0, 0), 127);
        int x1c = min(max(x0 + 1, 0), 127);
        const float* p00 = x + ((((y0c << 7) + x0c) << 7) + c0);
        const float* p01 = x + ((((y0c << 7) + x1c) << 7) + c0);
        const float* p10 = x + ((((y1c << 7) + x0c) << 7) + c0);
        const float* p11 = x + ((((y1c << 7) + x1c) << 7) + c0);
        v00 = *(const float4*)p00;
        v01 = *(const float4*)p01;
        v10 = *(const float4*)p10;
        v11 = *(const float4*)p11;
        u00 = *(const float4*)(p00 + 4);
        u01 = *(const float4*)(p01 + 4);
        u10 = *(const float4*)(p10 + 4);
        u11 = *(const float4*)(p11 + 4);
        const float* bp = Bptr + (size_t)k0 * 128;
        b0r = *(const float4*)bp;
        b1r = *(const float4*)(bp + 4);
    };

    gload(0);
    for (int k0 = 0; k0 < KDIM; k0 += 16) {
        float4 wg = w4_s[k0 >> 7][am];
        As[ak + 0][am] = wg.x * v00.x + wg.y * v01.x + wg.z * v10.x + wg.w * v11.x;
        As[ak + 1][am] = wg.x * v00.y + wg.y * v01.y + wg.z * v10.y + wg.w * v11.y;
        As[ak + 2][am] = wg.x * v00.z + wg.y * v01.z + wg.z * v10.z + wg.w * v11.z;
        As[ak + 3][am] = wg.x * v00.w + wg.y * v01.w + wg.z * v10.w + wg.w * v11.w;
        As[ak + 4][am] = wg.x * u00.x + wg.y * u01.x + wg.z * u10.x + wg.w * u11.x;
        As[ak + 5][am] = wg.x * u00.y + wg.y * u01.y + wg.z * u10.y + wg.w * u11.y;
        As[ak + 6][am] = wg.x * u00.z + wg.y * u01.z + wg.z * u10.z + wg.w * u11.z;
        As[ak + 7][am] = wg.x * u00.w + wg.y * u01.w + wg.z * u10.w + wg.w * u11.w;
        *(float4*)&Bs[bk][bn] = b0r;
        *(float4*)&Bs[bk][bn + 4] = b1r;
        __syncthreads();
        if (k0 + 16 < KDIM) gload(k0 + 16);
        mm16t<128>(As, Bs, acc, ty, tx);
        if (k0 + 16 < KDIM) __syncthreads();
    }

    float4 c0v = *(const float4*)&bias[tx * 8];
    float4 c1v = *(const float4*)&bias[tx * 8 + 4];
    float bb[8] = {c0v.x, c0v.y, c0v.z, c0v.w, c1v.x, c1v.y, c1v.z, c1v.w};
#pragma unroll
    for (int i = 0; i < 8; i++) {
        int p = (h << 7) + ty * 8 + i;
        float4 v0 = make_float4(acc[i][0] + bb[0], acc[i][1] + bb[1],
                                acc[i][2] + bb[2], acc[i][3] + bb[3]);
        float4 v1 = make_float4(acc[i][4] + bb[4], acc[i][5] + bb[5],
                                acc[i][6] + bb[6], acc[i][7] + bb[7]);
        *(float4*)&C[(size_t)p * 128 + tx * 8] = v0;
        *(float4*)&C[(size_t)p * 128 + tx * 8 + 4] = v1;
    }
}

// ------------- instance-norm: deterministic two-stage reduction (batched) ----
__global__ void __launch_bounds__(128) stats_part_kernel(const float* __restrict__ raw,
                                                         float* __restrict__ part) {
    const int img = blockIdx.y;
    raw += (size_t)img * IMGSTR;
    part += (size_t)img * 128 * CH * 2;
    int c = threadIdx.x;
    int b = blockIdx.x;
    float s = 0.f, q = 0.f;
    for (int p = b * 128; p < (b + 1) * 128; p++) {
        float v = raw[(size_t)p * 128 + c];
        s += v;
        q += v * v;
    }
    part[(size_t)(b * 128 + c) * 2 + 0] = s;
    part[(size_t)(b * 128 + c) * 2 + 1] = q;
}

__global__ void __launch_bounds__(128) stats_final_kernel(const float* __restrict__ part,
                                                          const float* __restrict__ bg,
                                                          const float* __restrict__ bb,
                                                          float* __restrict__ ab) {
    const int img = blockIdx.x;
    part += (size_t)img * 128 * CH * 2;
    ab += (size_t)img * CH * 2;
    int c = threadIdx.x;
    float s = 0.f, q = 0.f;
    for (int b = 0; b < 128; b++) {
        s += part[(size_t)(b * 128 + c) * 2 + 0];
        q += part[(size_t)(b * 128 + c) * 2 + 1];
    }
    float mu = s * (1.f / 16384.f);
    float var = q * (1.f / 16384.f) - mu * mu;
    float inv = rsqrtf(var + EPS);
    float a = inv * bg[c];
    ab[c * 2 + 0] = a;
    ab[c * 2 + 1] = bb[c] - mu * a;
}

__global__ void __launch_bounds__(256) norm_relu_kernel(const float* __restrict__ raw,
                                                        const float* __restrict__ ab,
                                                        float* __restrict__ y) {
    const int img = blockIdx.y;
    raw += (size_t)img * IMGSTR;
    y += (size_t)img * IMGSTR;
    ab += (size_t)img * CH * 2;
    int i = blockIdx.x * 256 + threadIdx.x;
    int c = i & 127;
    float v = raw[i] * ab[c * 2] + ab[c * 2 + 1];
    y[i] = v > 0.f ? v : 0.f;
}

// ------------- projection helpers (batched) ----------------------------------
__global__ void __launch_bounds__(128) acat_kernel(const float* __restrict__ xc,
                                                   Ptr5 xs, float* __restrict__ A) {
    const int img = blockIdx.y;
    xc += (size_t)img * IMGSTR;
    A += (size_t)img * NP * 256;
    const float* xin = xs.p[img];
    int p = blockIdx.x;
    int t = threadIdx.x;
    A[(size_t)p * 256 + t] = xc[(size_t)p * 128 + t];
    A[(size_t)p * 256 + 128 + t] = xin[(size_t)p * 128 + t];
}

// all-image padded projection weight: Bp[img][c][o], 256x384, zero padded
__global__ void bproj_kernel(Ptr5 wA, Ptr5 wB, float* __restrict__ Bp) {
    int i = blockIdx.x * 256 + threadIdx.x;   // 5*256*384 = 491520
    if (i >= IMG * 256 * 384) return;
    int img = i / (256 * 384);
    int r = i % (256 * 384);
    int o = r % 384;
    int c = r / 384;
    float v = 0.f;
    if (o < d_Co[img]) {
        if (c < 128) v = wA.p[img][o * 128 + c];
        else if (wB.p[img]) v = wB.p[img][o * 128 + (c - 128)];
    }
    Bp[i] = v;
}

// tmp[img][p][o] (384 stride) -> out NCHW at channel offset coff[img]
__global__ void proj_copy_kernel(const float* __restrict__ tmp, float* __restrict__ out) {
    const int img = blockIdx.y;
    int idx = blockIdx.x * 256 + threadIdx.x;   // up to 308*16384
    int Co = d_Co[img];
    if (idx >= Co * NP) return;
    int o = idx >> 14;
    int p = idx & 16383;
    out[(size_t)(d_coff[img] + o) * NP + p] =
        tmp[(size_t)img * NP * 384 + (size_t)p * 384 + o];
}

// ------------- final layernorm over W (rows of 128) --------------------------
__global__ void __launch_bounds__(256) final_ln_kernel(float* __restrict__ out,
                                                       const float* __restrict__ lnw,
                                                       const float* __restrict__ lnb) {
    int row = blockIdx.x * 8 + (threadIdx.x >> 5);  // 768*128 rows
    int lane = threadIdx.x & 31;
    float* rp = &out[(size_t)row * 128];
    float4 v = *(const float4*)&rp[lane * 4];
    float s = v.x + v.y + v.z + v.w;
    float q = v.x * v.x + v.y * v.y + v.z * v.z + v.w * v.w;
#pragma unroll
    for (int o = 16; o; o >>= 1) {
        s += __shfl_xor_sync(0xffffffffu, s, o);
        q += __shfl_xor_sync(0xffffffffu, q, o);
    }
    float mu = s * (1.f / 128.f);
    float var = q * (1.f / 128.f) - mu * mu;
    float inv = rsqrtf(var + EPS);
    float4 g = *(const float4*)&lnw[lane * 4];
    float4 b = *(const float4*)&lnb[lane * 4];
    v.x = (v.x - mu) * inv * g.x + b.x;
    v.y = (v.y - mu) * inv * g.y + b.y;
    v.z = (v.z - mu) * inv * g.z + b.z;
    v.w = (v.w - mu) * inv * g.w + b.w;
    *(float4*)&rp[lane * 4] = v;
}

// =============================================================================
#define SYM(p, s) do { void* _t = 0; cudaGetSymbolAddress(&_t, s); (p) = (float*)_t; } while (0)

static void run_block(Ptr5 xin, const float* wt, const float* cb,
                      const float* bg, const float* bb, float* yout,
                      float* pom, float* praw, float* ppart,
                      float* pab, float* powmw, float* poffm) {
    gemm_conv_kernel<<<dim3(256, IMG), 128>>>(xin, wt, cb, pom);
    gemm_kernel<<<dim3(256, 1, IMG), 128>>>(pom, powmw, 0, poffm, 128, 128,
                                            IMGSTR, 0, IMGSTR, 0);
    gemm_deform_kernel<<<dim3(128, IMG), 256>>>(xin, poffm, wt, cb, praw);
    stats_part_kernel<<<dim3(128, IMG), 128>>>(praw, ppart);
    stats_final_kernel<<<IMG, 128>>>(ppart, bg, bb, pab);
    norm_relu_kernel<<<dim3(IMGSTR / 256, IMG), 256>>>(praw, pab, yout);
}

extern "C" void kernel_launch(void* const* d_in, const int* in_sizes, int n_in,
                              void* d_out, int out_size) {
    (void)in_sizes; (void)n_in; (void)out_size;
    Ptr5 xs;
    for (int i = 0; i < 5; i++) xs.p[i] = (const float*)d_in[i];
    const float* b_cw[2] = {(const float*)d_in[5], (const float*)d_in[11]};
    const float* b_cb[2] = {(const float*)d_in[6], (const float*)d_in[12]};
    const float* b_ow[2] = {(const float*)d_in[7], (const float*)d_in[13]};
    const float* b_mw[2] = {(const float*)d_in[8], (const float*)d_in[14]};
    const float* b_bg[2] = {(const float*)d_in[9], (const float*)d_in[15]};
    const float* b_bb[2] = {(const float*)d_in[10], (const float*)d_in[16]};
    Ptr5 wA, wB;
    wA.p[0] = (const float*)d_in[17]; wB.p[0] = 0;
    wA.p[1] = (const float*)d_in[18]; wB.p[1] = 0;
    wA.p[2] = (const float*)d_in[19]; wB.p[2] = (const float*)d_in[20];
    wA.p[3] = (const float*)d_in[21]; wB.p[3] = (const float*)d_in[22];
    wA.p[4] = (const float*)d_in[23]; wB.p[4] = (const float*)d_in[24];
    const float* lnw = (const float*)d_in[25];
    const float* lnb = (const float*)d_in[26];
    float* out = (float*)d_out;

    float *pom, *praw, *py1, *py2, *pwt1, *pwt2, *ppart, *pab, *pacat,
          *pbproj, *pptmp, *powmw, *poffm;
    SYM(pom, g_om);   SYM(praw, g_raw);
    SYM(py1, g_y1);   SYM(py2, g_y2);   SYM(pwt1, g_wt1);  SYM(pwt2, g_wt2);
    SYM(ppart, g_part); SYM(pab, g_ab); SYM(pacat, g_acat);
    SYM(pbproj, g_bproj); SYM(pptmp, g_ptmp); SYM(powmw, g_owmw);
    SYM(poffm, g_offm);

    wt_kernel<<<576, 256>>>(b_cw[0], pwt1);
    wt_kernel<<<576, 256>>>(b_cw[1], pwt2);

    Ptr5 y1p;
    for (int i = 0; i < 5; i++) y1p.p[i] = py1 + (size_t)i * IMGSTR;

    // block 1 (all images)
    padow_kernel<<<64, 256>>>(b_ow[0], b_mw[0], powmw);
    run_block(xs, pwt1, b_cb[0], b_bg[0], b_bb[0], py1,
              pom, praw, ppart, pab, powmw, poffm);
    // block 2 (all images)
    padow_kernel<<<64, 256>>>(b_ow[1], b_mw[1], powmw);
    run_block(y1p, pwt2, b_cb[1], b_bg[1], b_bb[1], py2,
              pom, praw, ppart, pab, powmw, poffm);

    // projections (batched, padded to 256x384 with per-image tile guard)
    acat_kernel<<<dim3(NP, IMG), 128>>>(py2, xs, pacat);
    bproj_kernel<<<(IMG * 256 * 384 + 255) / 256, 256>>>(wA, wB, pbproj);
    gemm_kernel<<<dim3(256, 3, IMG), 128>>>(pacat, pbproj, 0, pptmp, 256, 384,
                                            (size_t)NP * 256, 256 * 384,
                                            (size_t)NP * 384, 1);
    proj_copy_kernel<<<dim3((308 * NP + 255) / 256, IMG), 256>>>(pptmp, out);
    final_ln_kernel<<<768 * 128 / 8, 256>>>(out, lnw, lnb);
}

// round 11
// speedup vs baseline: 1.5791x; 1.0480x over previous
#include <cuda_runtime.h>
#include <math.h>

// Problem constants
#define HH 128
#define WW 128
#define CH 128
#define NP 16384          // H*W pixels
#define KK 9
#define KDIM 1152         // 9*128
#define EPS 1e-5f
#define IMG 5
#define IMGSTR (NP * CH)  // per-image plane stride (2M floats)

struct Ptr5 { const float* p[5]; };

__device__ const int d_Co[5]   = {20, 80, 150, 210, 308};
__device__ const int d_coff[5] = {0, 20, 100, 250, 460};
__device__ const int d_Npad[5] = {128, 128, 256, 256, 384};

// ---------------- scratch (static device globals; no allocation) -------------
__device__ float g_om[IMG * IMGSTR];      // conv3x3 outputs
__device__ float g_raw[IMG * IMGSTR];     // pre-norm deform outputs
__device__ float g_y1[IMG * IMGSTR];      // block1 outputs
__device__ float g_y2[IMG * IMGSTR];      // block2 outputs
__device__ float g_offm[IMG * IMGSTR];    // offset/mask logits (padded 128)
__device__ float g_wt1[KK * CH * CH];     // transposed conv weights, block1
__device__ float g_wt2[KK * CH * CH];     // transposed conv weights, block2
__device__ float g_owmw[CH * 128];        // padded offset/mask weight [c][j]
__device__ float g_part[IMG * 128 * CH * 2];
__device__ float g_ab[IMG * CH * 2];
__device__ float g_acat[IMG * NP * 256];  // [xc | xin]
__device__ float g_bproj[IMG * 256 * 384];
__device__ float g_ptmp[IMG * NP * 384];  // projection GEMM outputs

// ---------------- weight transpose: cw (O,C,3,3) -> wt[k][c][o] --------------
__global__ void wt_kernel(const float* __restrict__ cw, float* __restrict__ wt) {
    int i = blockIdx.x * 256 + threadIdx.x;   // KK*CH*CH = 147456
    if (i >= KK * CH * CH) return;
    int o = i & 127;
    int kc = i >> 7;
    int c = kc & 127;
    int k = kc >> 7;
    wt[i] = cw[((o << 7) + c) * 9 + k];
}

// ------ pad offset/mask weights: B[c][j] = ow[j][c] (j<18) / mw[j-18][c] -----
__global__ void padow_kernel(const float* __restrict__ ow, const float* __restrict__ mw,
                             float* __restrict__ Bp) {
    int i = blockIdx.x * 256 + threadIdx.x;   // 16384
    int j = i & 127;
    int c = i >> 7;
    float v = 0.f;
    if (j < 18) v = ow[j * 128 + c];
    else if (j < 27) v = mw[(j - 18) * 128 + c];
    Bp[i] = v;
}

// ---- packed-f32x2 16-step FMA block on one (As,Bs) stage --------------------
// acc[i][j] is a packed pair (cols tx*8+2j, tx*8+2j+1). Per-lane math is exact
// fp32 FMA in the same order as the scalar version -> bit-identical results.
template <int AW>
__device__ __forceinline__ void mm16x2(const float (*__restrict__ As)[AW],
                                       const float (*__restrict__ Bs)[128],
                                       unsigned long long acc[8][4],
                                       int ty, int tx) {
#pragma unroll
    for (int kk = 0; kk < 16; kk++) {
        float4 av0 = *(const float4*)&As[kk][ty * 8];
        float4 av1 = *(const float4*)&As[kk][ty * 8 + 4];
        ulonglong2 bq0 = *(const ulonglong2*)&Bs[kk][tx * 8];
        ulonglong2 bq1 = *(const ulonglong2*)&Bs[kk][tx * 8 + 4];
        unsigned long long b[4] = {bq0.x, bq0.y, bq1.x, bq1.y};
        float a[8] = {av0.x, av0.y, av0.z, av0.w, av1.x, av1.y, av1.z, av1.w};
#pragma unroll
        for (int i = 0; i < 8; i++) {
            unsigned long long ad;
            asm("mov.b64 %0, {%1, %1};" : "=l"(ad) : "f"(a[i]));
#pragma unroll
            for (int j = 0; j < 4; j++)
                asm("fma.rn.f32x2 %0, %1, %2, %0;"
                    : "+l"(acc[i][j]) : "l"(ad), "l"(b[j]));
        }
    }
}

__device__ __forceinline__ void unpack2(unsigned long long p, float& lo, float& hi) {
    asm("mov.b64 {%0, %1}, %2;" : "=f"(lo), "=f"(hi) : "l"(p));
}

// =========== batched tiled fp32 GEMM =========================================
// C[img][M,Ntot] = A[img][M,Kd] @ B[img][Kd,Ntot]; grid (Mtiles, Ntiles, IMG).
// 128x128 tile, 256 threads, double-buffered, FFMA2 inner loop.
__global__ void __launch_bounds__(256) gemm_kernel(const float* __restrict__ A,
                                                   const float* __restrict__ B,
                                                   const float* __restrict__ bias,
                                                   float* __restrict__ C,
                                                   int Kd, int Ntot,
                                                   size_t Astr, size_t Bstr, size_t Cstr,
                                                   int use_nguard) {
    const int img = blockIdx.z;
    if (use_nguard && (int)(blockIdx.y * 128) >= d_Npad[img]) return;
    A += (size_t)img * Astr;
    B += (size_t)img * Bstr;
    C += (size_t)img * Cstr;
    __shared__ float As[2][16][128];
    __shared__ float Bs[2][16][128];
    const int tid = threadIdx.x;
    const int row0 = blockIdx.x * 128;
    const int col0 = blockIdx.y * 128;
    const int tx = tid & 15;
    const int ty = tid >> 4;
    const int am = tid >> 1;
    const int ak = (tid & 1) << 3;
    const int bk = tid >> 4;
    const int bn = (tid & 15) << 3;

    unsigned long long acc[8][4];
#pragma unroll
    for (int i = 0; i < 8; i++)
#pragma unroll
        for (int j = 0; j < 4; j++) acc[i][j] = 0ull;

    const float* Aptr = A + (size_t)(row0 + am) * Kd + ak;
    const float* Bptr = B + (size_t)bk * Ntot + col0 + bn;

    float4 a0 = *(const float4*)(Aptr);
    float4 a1 = *(const float4*)(Aptr + 4);
    float4 b0 = *(const float4*)(Bptr);
    float4 b1 = *(const float4*)(Bptr + 4);
    As[0][ak + 0][am] = a0.x; As[0][ak + 1][am] = a0.y;
    As[0][ak + 2][am] = a0.z; As[0][ak + 3][am] = a0.w;
    As[0][ak + 4][am] = a1.x; As[0][ak + 5][am] = a1.y;
    As[0][ak + 6][am] = a1.z; As[0][ak + 7][am] = a1.w;
    *(float4*)&Bs[0][bk][bn] = b0;
    *(float4*)&Bs[0][bk][bn + 4] = b1;
    __syncthreads();

    int buf = 0;
    for (int k0 = 16; k0 < Kd; k0 += 16) {
        a0 = *(const float4*)(Aptr + k0);
        a1 = *(const float4*)(Aptr + k0 + 4);
        const float* bp = Bptr + (size_t)k0 * Ntot;
        b0 = *(const float4*)bp;
        b1 = *(const float4*)(bp + 4);
        mm16x2<128>(As[buf], Bs[buf], acc, ty, tx);
        int nb = buf ^ 1;
        As[nb][ak + 0][am] = a0.x; As[nb][ak + 1][am] = a0.y;
        As[nb][ak + 2][am] = a0.z; As[nb][ak + 3][am] = a0.w;
        As[nb][ak + 4][am] = a1.x; As[nb][ak + 5][am] = a1.y;
        As[nb][ak + 6][am] = a1.z; As[nb][ak + 7][am] = a1.w;
        *(float4*)&Bs[nb][bk][bn] = b0;
        *(float4*)&Bs[nb][bk][bn + 4] = b1;
        __syncthreads();
        buf = nb;
    }
    mm16x2<128>(As[buf], Bs[buf], acc, ty, tx);

    float bb[8] = {0.f, 0.f, 0.f, 0.f, 0.f, 0.f, 0.f, 0.f};
    if (bias) {
        float4 c0 = *(const float4*)&bias[col0 + tx * 8];
        float4 c1 = *(const float4*)&bias[col0 + tx * 8 + 4];
        bb[0] = c0.x; bb[1] = c0.y; bb[2] = c0.z; bb[3] = c0.w;
        bb[4] = c1.x; bb[5] = c1.y; bb[6] = c1.z; bb[7] = c1.w;
    }
#pragma unroll
    for (int i = 0; i < 8; i++) {
        int row = row0 + ty * 8 + i;
        float r[8];
        unpack2(acc[i][0], r[0], r[1]);
        unpack2(acc[i][1], r[2], r[3]);
        unpack2(acc[i][2], r[4], r[5]);
        unpack2(acc[i][3], r[6], r[7]);
        float4 v0 = make_float4(r[0] + bb[0], r[1] + bb[1], r[2] + bb[2], r[3] + bb[3]);
        float4 v1 = make_float4(r[4] + bb[4], r[5] + bb[5], r[6] + bb[6], r[7] + bb[7]);
        *(float4*)&C[(size_t)row * Ntot + col0 + tx * 8] = v0;
        *(float4*)&C[(size_t)row * Ntot + col0 + tx * 8 + 4] = v1;
    }
}

// ====== batched fused im2col conv3x3 GEMM: grid (128 rows, IMG) ==============
__global__ void __launch_bounds__(256) gemm_conv_kernel(Ptr5 xs,
                                                        const float* __restrict__ B,
                                                        const float* __restrict__ bias,
                                                        float* __restrict__ C) {
    const int img = blockIdx.y;
    const float* __restrict__ x = xs.p[img];
    C += (size_t)img * IMGSTR;
    __shared__ float As[2][16][128];
    __shared__ float Bs[2][16][128];
    const int tid = threadIdx.x;
    const int h = blockIdx.x;
    const int tx = tid & 15;
    const int ty = tid >> 4;
    const int am = tid >> 1;
    const int ak = (tid & 1) << 3;
    const int bk = tid >> 4;
    const int bn = (tid & 15) << 3;

    unsigned long long acc[8][4];
#pragma unroll
    for (int i = 0; i < 8; i++)
#pragma unroll
        for (int j = 0; j < 4; j++) acc[i][j] = 0ull;

    const float* Bptr = B + (size_t)bk * 128 + bn;

    auto loadA = [&](int k0, float4& o0, float4& o1) {
        int tap = k0 >> 7;
        int c0 = (k0 & 127) + ak;
        int hh = h + tap / 3 - 1;
        int wcol = am + tap % 3 - 1;
        o0 = make_float4(0.f, 0.f, 0.f, 0.f);
        o1 = make_float4(0.f, 0.f, 0.f, 0.f);
        if ((unsigned)hh < 128u && (unsigned)wcol < 128u) {
            const float* xp = x + ((((hh << 7) + wcol)) << 7) + c0;
            o0 = *(const float4*)xp;
            o1 = *(const float4*)(xp + 4);
        }
    };

    float4 a0, a1;
    loadA(0, a0, a1);
    float4 b0 = *(const float4*)(Bptr);
    float4 b1 = *(const float4*)(Bptr + 4);
    As[0][ak + 0][am] = a0.x; As[0][ak + 1][am] = a0.y;
    As[0][ak + 2][am] = a0.z; As[0][ak + 3][am] = a0.w;
    As[0][ak + 4][am] = a1.x; As[0][ak + 5][am] = a1.y;
    As[0][ak + 6][am] = a1.z; As[0][ak + 7][am] = a1.w;
    *(float4*)&Bs[0][bk][bn] = b0;
    *(float4*)&Bs[0][bk][bn + 4] = b1;
    __syncthreads();

    int buf = 0;
    for (int k0 = 16; k0 < KDIM; k0 += 16) {
        loadA(k0, a0, a1);
        const float* bp = Bptr + (size_t)k0 * 128;
        b0 = *(const float4*)bp;
        b1 = *(const float4*)(bp + 4);
        mm16x2<128>(As[buf], Bs[buf], acc, ty, tx);
        int nb = buf ^ 1;
        As[nb][ak + 0][am] = a0.x; As[nb][ak + 1][am] = a0.y;
        As[nb][ak + 2][am] = a0.z; As[nb][ak + 3][am] = a0.w;
        As[nb][ak + 4][am] = a1.x; As[nb][ak + 5][am] = a1.y;
        As[nb][ak + 6][am] = a1.z; As[nb][ak + 7][am] = a1.w;
        *(float4*)&Bs[nb][bk][bn] = b0;
        *(float4*)&Bs[nb][bk][bn + 4] = b1;
        __syncthreads();
        buf = nb;
    }
    mm16x2<128>(As[buf], Bs[buf], acc, ty, tx);

    float4 c0 = *(const float4*)&bias[tx * 8];
    float4 c1 = *(const float4*)&bias[tx * 8 + 4];
    float bb[8] = {c0.x, c0.y, c0.z, c0.w, c1.x, c1.y, c1.z, c1.w};
#pragma unroll
    for (int i = 0; i < 8; i++) {
        int p = (h << 7) + ty * 8 + i;
        float r[8];
        unpack2(acc[i][0], r[0], r[1]);
        unpack2(acc[i][1], r[2], r[3]);
        unpack2(acc[i][2], r[4], r[5]);
        unpack2(acc[i][3], r[6], r[7]);
        float4 v0 = make_float4(r[0] + bb[0], r[1] + bb[1], r[2] + bb[2], r[3] + bb[3]);
        float4 v1 = make_float4(r[4] + bb[4], r[5] + bb[5], r[6] + bb[6], r[7] + bb[7]);
        *(float4*)&C[(size_t)p * 128 + tx * 8] = v0;
        *(float4*)&C[(size_t)p * 128 + tx * 8 + 4] = v1;
    }
}

// ====== batched fused deformable-sample GEMM: grid (128 rows, IMG) ===========
// Software-pipelined gathers; FFMA2 inner loop.
__global__ void __launch_bounds__(256) gemm_deform_kernel(Ptr5 xs,
                                                          const float* __restrict__ offm,
                                                          const float* __restrict__ B,
                                                          const float* __restrict__ bias,
                                                          float* __restrict__ C) {
    const int img = blockIdx.y;
    const float* __restrict__ x = xs.p[img];
    offm += (size_t)img * IMGSTR;
    C += (size_t)img * IMGSTR;
    __shared__ float As[16][128];
    __shared__ float Bs[16][128];
    __shared__ float4 w4_s[9][128];
    __shared__ int iy_s[9][128];
    __shared__ int ix_s[9][128];
    const int tid = threadIdx.x;
    const int h = blockIdx.x;
    const int tx = tid & 15;
    const int ty = tid >> 4;
    const int am = tid >> 1;
    const int ak = (tid & 1) << 3;
    const int bk = tid >> 4;
    const int bn = (tid & 15) << 3;

    if (tid < 128) {
        int w = tid;
        const float* d = &offm[((size_t)((h << 7) + w)) * 128];
        float mx = d[18];
#pragma unroll
        for (int k = 1; k < 9; k++) mx = fmaxf(mx, d[18 + k]);
        float e[9];
        float ssum = 0.f;
#pragma unroll
        for (int k = 0; k < 9; k++) { e[k] = expf(d[18 + k] - mx); ssum += e[k]; }
        float r = 1.f / ssum;
#pragma unroll
        for (int k = 0; k < 9; k++) {
            float m = e[k] * r;
            float py = (float)(h - 1 + k / 3) + d[2 * k];
            float px = (float)(w - 1 + k % 3) + d[2 * k + 1];
            float y0f = floorf(py), x0f = floorf(px);
            float wy1 = py - y0f, wy0 = 1.f - wy1;
            float wx1 = px - x0f, wx0 = 1.f - wx1;
            int y0 = (int)y0f, x0 = (int)x0f;
            float vy0 = ((unsigned)y0 < 128u) ? 1.f : 0.f;
            float vy1 = ((unsigned)(y0 + 1) < 128u) ? 1.f : 0.f;
            float vx0 = ((unsigned)x0 < 128u) ? 1.f : 0.f;
            float vx1 = ((unsigned)(x0 + 1) < 128u) ? 1.f : 0.f;
            w4_s[k][w] = make_float4(wy0 * wx0 * vy0 * vx0 * m,
                                     wy0 * wx1 * vy0 * vx1 * m,
                                     wy1 * wx0 * vy1 * vx0 * m,
                                     wy1 * wx1 * vy1 * vx1 * m);
            iy_s[k][w] = y0;
            ix_s[k][w] = x0;
        }
    }
    __syncthreads();

    unsigned long long acc[8][4];
#pragma unroll
    for (int i = 0; i < 8; i++)
#pragma unroll
        for (int j = 0; j < 4; j++) acc[i][j] = 0ull;

    const float* Bptr = B + (size_t)bk * 128 + bn;

    float4 v00, v01, v10, v11, u00, u01, u10, u11, b0r, b1r;
    auto gload = [&](int k0) {
        int tap = k0 >> 7;
        int c0 = (k0 & 127) + ak;
        int y0 = iy_s[tap][am];
        int x0 = ix_s[tap][am];
        int y0c = min(max(y0, 0), 127);
        int y1c = min(max(y0 + 1, 0), 127);
        int x0c = min(max(x0, 0), 127);
        int x1c = min(max(x0 + 1, 0), 127);
        const float* p00 = x + ((((y0c << 7) + x0c) << 7) + c0);
        const float* p01 = x + ((((y0c << 7) + x1c) << 7) + c0);
        const float* p10 = x + ((((y1c << 7) + x0c) << 7) + c0);
        const float* p11 = x + ((((y1c << 7) + x1c) << 7) + c0);
        v00 = *(const float4*)p00;
        v01 = *(const float4*)p01;
        v10 = *(const float4*)p10;
        v11 = *(const float4*)p11;
        u00 = *(const float4*)(p00 + 4);
        u01 = *(const float4*)(p01 + 4);
        u10 = *(const float4*)(p10 + 4);
        u11 = *(const float4*)(p11 + 4);
        const float* bp = Bptr + (size_t)k0 * 128;
        b0r = *(const float4*)bp;
        b1r = *(const float4*)(bp + 4);
    };

    gload(0);
    for (int k0 = 0; k0 < KDIM; k0 += 16) {
        float4 wg = w4_s[k0 >> 7][am];
        As[ak + 0][am] = wg.x * v00.x + wg.y * v01.x + wg.z * v10.x + wg.w * v11.x;
        As[ak + 1][am] = wg.x * v00.y + wg.y * v01.y + wg.z * v10.y + wg.w * v11.y;
        As[ak + 2][am] = wg.x * v00.z + wg.y * v01.z + wg.z * v10.z + wg.w * v11.z;
        As[ak + 3][am] = wg.x * v00.w + wg.y * v01.w + wg.z * v10.w + wg.w * v11.w;
        As[ak + 4][am] = wg.x * u00.x + wg.y * u01.x + wg.z * u10.x + wg.w * u11.x;
        As[ak + 5][am] = wg.x * u00.y + wg.y * u01.y + wg.z * u10.y + wg.w * u11.y;
        As[ak + 6][am] = wg.x * u00.z + wg.y * u01.z + wg.z * u10.z + wg.w * u11.z;
        As[ak + 7][am] = wg.x * u00.w + wg.y * u01.w + wg.z * u10.w + wg.w * u11.w;
        *(float4*)&Bs[bk][bn] = b0r;
        *(float4*)&Bs[bk][bn + 4] = b1r;
        __syncthreads();
        if (k0 + 16 < KDIM) gload(k0 + 16);
        mm16x2<128>(As, Bs, acc, ty, tx);
        if (k0 + 16 < KDIM) __syncthreads();
    }

    float4 c0v = *(const float4*)&bias[tx * 8];
    float4 c1v = *(const float4*)&bias[tx * 8 + 4];
    float bb[8] = {c0v.x, c0v.y, c0v.z, c0v.w, c1v.x, c1v.y, c1v.z, c1v.w};
#pragma unroll
    for (int i = 0; i < 8; i++) {
        int p = (h << 7) + ty * 8 + i;
        float r[8];
        unpack2(acc[i][0], r[0], r[1]);
        unpack2(acc[i][1], r[2], r[3]);
        unpack2(acc[i][2], r[4], r[5]);
        unpack2(acc[i][3], r[6], r[7]);
        float4 v0 = make_float4(r[0] + bb[0], r[1] + bb[1], r[2] + bb[2], r[3] + bb[3]);
        float4 v1 = make_float4(r[4] + bb[4], r[5] + bb[5], r[6] + bb[6], r[7] + bb[7]);
        *(float4*)&C[(size_t)p * 128 + tx * 8] = v0;
        *(float4*)&C[(size_t)p * 128 + tx * 8 + 4] = v1;
    }
}

// ------------- instance-norm: deterministic two-stage reduction (batched) ----
__global__ void __launch_bounds__(128) stats_part_kernel(const float* __restrict__ raw,
                                                         float* __restrict__ part) {
    const int img = blockIdx.y;
    raw += (size_t)img * IMGSTR;
    part += (size_t)img * 128 * CH * 2;
    int c = threadIdx.x;
    int b = blockIdx.x;
    float s = 0.f, q = 0.f;
    for (int p = b * 128; p < (b + 1) * 128; p++) {
        float v = raw[(size_t)p * 128 + c];
        s += v;
        q += v * v;
    }
    part[(size_t)(b * 128 + c) * 2 + 0] = s;
    part[(size_t)(b * 128 + c) * 2 + 1] = q;
}

__global__ void __launch_bounds__(128) stats_final_kernel(const float* __restrict__ part,
                                                          const float* __restrict__ bg,
                                                          const float* __restrict__ bb,
                                                          float* __restrict__ ab) {
    const int img = blockIdx.x;
    part += (size_t)img * 128 * CH * 2;
    ab += (size_t)img * CH * 2;
    int c = threadIdx.x;
    float s = 0.f, q = 0.f;
    for (int b = 0; b < 128; b++) {
        s += part[(size_t)(b * 128 + c) * 2 + 0];
        q += part[(size_t)(b * 128 + c) * 2 + 1];
    }
    float mu = s * (1.f / 16384.f);
    float var = q * (1.f / 16384.f) - mu * mu;
    float inv = rsqrtf(var + EPS);
    float a = inv * bg[c];
    ab[c * 2 + 0] = a;
    ab[c * 2 + 1] = bb[c] - mu * a;
}

__global__ void __launch_bounds__(256) norm_relu_kernel(const float* __restrict__ raw,
                                                        const float* __restrict__ ab,
                                                        float* __restrict__ y) {
    const int img = blockIdx.y;
    raw += (size_t)img * IMGSTR;
    y += (size_t)img * IMGSTR;
    ab += (size_t)img * CH * 2;
    int i = blockIdx.x * 256 + threadIdx.x;
    int c = i & 127;
    float v = raw[i] * ab[c * 2] + ab[c * 2 + 1];
    y[i] = v > 0.f ? v : 0.f;
}

// ------------- projection helpers (batched) ----------------------------------
__global__ void __launch_bounds__(128) acat_kernel(const float* __restrict__ xc,
                                                   Ptr5 xs, float* __restrict__ A) {
    const int img = blockIdx.y;
    xc += (size_t)img * IMGSTR;
    A += (size_t)img * NP * 256;
    const float* xin = xs.p[img];
    int p = blockIdx.x;
    int t = threadIdx.x;
    A[(size_t)p * 256 + t] = xc[(size_t)p * 128 + t];
    A[(size_t)p * 256 + 128 + t] = xin[(size_t)p * 128 + t];
}

// all-image padded projection weight: Bp[img][c][o], 256x384, zero padded
__global__ void bproj_kernel(Ptr5 wA, Ptr5 wB, float* __restrict__ Bp) {
    int i = blockIdx.x * 256 + threadIdx.x;   // 5*256*384 = 491520
    if (i >= IMG * 256 * 384) return;
    int img = i / (256 * 384);
    int r = i % (256 * 384);
    int o = r % 384;
    int c = r / 384;
    float v = 0.f;
    if (o < d_Co[img]) {
        if (c < 128) v = wA.p[img][o * 128 + c];
        else if (wB.p[img]) v = wB.p[img][o * 128 + (c - 128)];
    }
    Bp[i] = v;
}

// tmp[img][p][o] (384 stride) -> out NCHW at channel offset coff[img]
__global__ void proj_copy_kernel(const float* __restrict__ tmp, float* __restrict__ out) {
    const int img = blockIdx.y;
    int idx = blockIdx.x * 256 + threadIdx.x;   // up to 308*16384
    int Co = d_Co[img];
    if (idx >= Co * NP) return;
    int o = idx >> 14;
    int p = idx & 16383;
    out[(size_t)(d_coff[img] + o) * NP + p] =
        tmp[(size_t)img * NP * 384 + (size_t)p * 384 + o];
}

// ------------- final layernorm over W (rows of 128) --------------------------
__global__ void __launch_bounds__(256) final_ln_kernel(float* __restrict__ out,
                                                       const float* __restrict__ lnw,
                                                       const float* __restrict__ lnb) {
    int row = blockIdx.x * 8 + (threadIdx.x >> 5);  // 768*128 rows
    int lane = threadIdx.x & 31;
    float* rp = &out[(size_t)row * 128];
    float4 v = *(const float4*)&rp[lane * 4];
    float s = v.x + v.y + v.z + v.w;
    float q = v.x * v.x + v.y * v.y + v.z * v.z + v.w * v.w;
#pragma unroll
    for (int o = 16; o; o >>= 1) {
        s += __shfl_xor_sync(0xffffffffu, s, o);
        q += __shfl_xor_sync(0xffffffffu, q, o);
    }
    float mu = s * (1.f / 128.f);
    float var = q * (1.f / 128.f) - mu * mu;
    float inv = rsqrtf(var + EPS);
    float4 g = *(const float4*)&lnw[lane * 4];
    float4 b = *(const float4*)&lnb[lane * 4];
    v.x = (v.x - mu) * inv * g.x + b.x;
    v.y = (v.y - mu) * inv * g.y + b.y;
    v.z = (v.z - mu) * inv * g.z + b.z;
    v.w = (v.w - mu) * inv * g.w + b.w;
    *(float4*)&rp[lane * 4] = v;
}

// =============================================================================
#define SYM(p, s) do { void* _t = 0; cudaGetSymbolAddress(&_t, s); (p) = (float*)_t; } while (0)

static void run_block(Ptr5 xin, const float* wt, const float* cb,
                      const float* bg, const float* bb, float* yout,
                      float* pom, float* praw, float* ppart,
                      float* pab, float* powmw, float* poffm) {
    gemm_conv_kernel<<<dim3(128, IMG), 256>>>(xin, wt, cb, pom);
    gemm_kernel<<<dim3(128, 1, IMG), 256>>>(pom, powmw, 0, poffm, 128, 128,
                                            IMGSTR, 0, IMGSTR, 0);
    gemm_deform_kernel<<<dim3(128, IMG), 256>>>(xin, poffm, wt, cb, praw);
    stats_part_kernel<<<dim3(128, IMG), 128>>>(praw, ppart);
    stats_final_kernel<<<IMG, 128>>>(ppart, bg, bb, pab);
    norm_relu_kernel<<<dim3(IMGSTR / 256, IMG), 256>>>(praw, pab, yout);
}

extern "C" void kernel_launch(void* const* d_in, const int* in_sizes, int n_in,
                              void* d_out, int out_size) {
    (void)in_sizes; (void)n_in; (void)out_size;
    Ptr5 xs;
    for (int i = 0; i < 5; i++) xs.p[i] = (const float*)d_in[i];
    const float* b_cw[2] = {(const float*)d_in[5], (const float*)d_in[11]};
    const float* b_cb[2] = {(const float*)d_in[6], (const float*)d_in[12]};
    const float* b_ow[2] = {(const float*)d_in[7], (const float*)d_in[13]};
    const float* b_mw[2] = {(const float*)d_in[8], (const float*)d_in[14]};
    const float* b_bg[2] = {(const float*)d_in[9], (const float*)d_in[15]};
    const float* b_bb[2] = {(const float*)d_in[10], (const float*)d_in[16]};
    Ptr5 wA, wB;
    wA.p[0] = (const float*)d_in[17]; wB.p[0] = 0;
    wA.p[1] = (const float*)d_in[18]; wB.p[1] = 0;
    wA.p[2] = (const float*)d_in[19]; wB.p[2] = (const float*)d_in[20];
    wA.p[3] = (const float*)d_in[21]; wB.p[3] = (const float*)d_in[22];
    wA.p[4] = (const float*)d_in[23]; wB.p[4] = (const float*)d_in[24];
    const float* lnw = (const float*)d_in[25];
    const float* lnb = (const float*)d_in[26];
    float* out = (float*)d_out;

    float *pom, *praw, *py1, *py2, *pwt1, *pwt2, *ppart, *pab, *pacat,
          *pbproj, *pptmp, *powmw, *poffm;
    SYM(pom, g_om);   SYM(praw, g_raw);
    SYM(py1, g_y1);   SYM(py2, g_y2);   SYM(pwt1, g_wt1);  SYM(pwt2, g_wt2);
    SYM(ppart, g_part); SYM(pab, g_ab); SYM(pacat, g_acat);
    SYM(pbproj, g_bproj); SYM(pptmp, g_ptmp); SYM(powmw, g_owmw);
    SYM(poffm, g_offm);

    wt_kernel<<<576, 256>>>(b_cw[0], pwt1);
    wt_kernel<<<576, 256>>>(b_cw[1], pwt2);

    Ptr5 y1p;
    for (int i = 0; i < 5; i++) y1p.p[i] = py1 + (size_t)i * IMGSTR;

    // block 1 (all images)
    padow_kernel<<<64, 256>>>(b_ow[0], b_mw[0], powmw);
    run_block(xs, pwt1, b_cb[0], b_bg[0], b_bb[0], py1,
              pom, praw, ppart, pab, powmw, poffm);
    // block 2 (all images)
    padow_kernel<<<64, 256>>>(b_ow[1], b_mw[1], powmw);
    run_block(y1p, pwt2, b_cb[1], b_bg[1], b_bb[1], py2,
              pom, praw, ppart, pab, powmw, poffm);

    // projections (batched, padded to 256x384 with per-image tile guard)
    acat_kernel<<<dim3(NP, IMG), 128>>>(py2, xs, pacat);
    bproj_kernel<<<(IMG * 256 * 384 + 255) / 256, 256>>>(wA, wB, pbproj);
    gemm_kernel<<<dim3(128, 3, IMG), 256>>>(pacat, pbproj, 0, pptmp, 256, 384,
                                            (size_t)NP * 256, 256 * 384,
                                            (size_t)NP * 384, 1);
    proj_copy_kernel<<<dim3((308 * NP + 255) / 256, IMG), 256>>>(pptmp, out);
    final_ln_kernel<<<768 * 128 / 8, 256>>>(out, lnw, lnb);
}